// round 12
// baseline (speedup 1.0000x reference)
#include <cuda_runtime.h>
#include <cuda_fp16.h>
#include <cstdint>

#define MAXN 50000
#define MAXE 800000
#define HDIM 96
#define HDIM2 192
#define MAXF 512

// ---------------- scratch (device globals; no allocation allowed) ----------------
__device__ int    g_deg_in[MAXN];
__device__ int    g_deg_out[MAXN];
__device__ int    g_fill[MAXN];
__device__ int    g_rowptr[MAXN + 1];
__device__ int2   g_col2[MAXE];                 // {src, perm[src]} per edge (CSR by dst)
__device__ float  g_norm_in[MAXN];
__device__ float  g_norm_out[MAXN];
__device__ __half g_Yh[(size_t)MAXN * HDIM];    // x @ W1, fp16 (gather source)
__device__ __half g_HBh[(size_t)MAXN * HDIM2];  // layer-2 features, fp16 (gather source)
__device__ float  g_P[(size_t)MAXN * HDIM2];    // layer-1 post-PReLU, tf32-rounded fp32
__device__ float  g_W1c[MAXF * HDIM];           // W1 pre-converted to tf32 bits
__device__ float  g_W2c[HDIM * HDIM];           // W2 pre-converted to tf32 bits
__device__ float  g_wsum[HDIM];
__device__ float  g_bmsum;

// ---------------- tf32 / cp.async helpers ----------------
__device__ __forceinline__ uint32_t f2tf32(float x) {
    uint32_t u;
    asm("cvt.rna.tf32.f32 %0, %1;" : "=r"(u) : "f"(x));
    return u;
}
__device__ __forceinline__ void mma_tf32(float* c, const uint32_t* a,
                                         uint32_t b0, uint32_t b1) {
    asm volatile(
        "mma.sync.aligned.m16n8k8.row.col.f32.tf32.tf32.f32 "
        "{%0,%1,%2,%3},{%4,%5,%6,%7},{%8,%9},{%0,%1,%2,%3};"
        : "+f"(c[0]), "+f"(c[1]), "+f"(c[2]), "+f"(c[3])
        : "r"(a[0]), "r"(a[1]), "r"(a[2]), "r"(a[3]), "r"(b0), "r"(b1));
}
__device__ __forceinline__ uint32_t smem_u32(const void* p) {
    uint32_t a;
    asm("{ .reg .u64 t; cvta.to.shared.u64 t, %1; cvt.u32.u64 %0, t; }" : "=r"(a) : "l"(p));
    return a;
}
// 16B async copy; sz=0 -> zero-fill destination
__device__ __forceinline__ void cpa16(uint32_t saddr, const void* gaddr, uint32_t sz) {
    asm volatile("cp.async.cg.shared.global [%0], [%1], 16, %2;"
                 :: "r"(saddr), "l"(gaddr), "r"(sz));
}
#define CP_COMMIT() asm volatile("cp.async.commit_group;" ::: "memory")
#define CP_WAIT1()  asm volatile("cp.async.wait_group 1;" ::: "memory")

// ---------------- small setup kernels ----------------
__global__ void degree_kernel(const int* __restrict__ src, const int* __restrict__ dst, int e) {
    int i = blockIdx.x * blockDim.x + threadIdx.x;
    if (i < e) {
        atomicAdd(&g_deg_out[src[i]], 1);
        atomicAdd(&g_deg_in[dst[i]], 1);
    }
}

__global__ void scan_kernel(int n, const float* __restrict__ Wm, const float* __restrict__ bm) {
    __shared__ int ssum[1024];
    int t = threadIdx.x;

    if (t < HDIM) {
        float s = 0.f;
        #pragma unroll 8
        for (int j = 0; j < HDIM; j++) s += Wm[t * HDIM + j];
        g_wsum[t] = s;
    }
    if (t == 0) {
        float s = 0.f;
        for (int j = 0; j < HDIM; j++) s += bm[j];
        g_bmsum = s;
    }

    int chunk = (n + 1023) / 1024;
    int beg = min(t * chunk, n);
    int end = min(beg + chunk, n);
    int s = 0;
    for (int i = beg; i < end; i++) s += g_deg_in[i];
    ssum[t] = s;
    __syncthreads();
    for (int off = 1; off < 1024; off <<= 1) {
        int v = (t >= off) ? ssum[t - off] : 0;
        __syncthreads();
        ssum[t] += v;
        __syncthreads();
    }
    int run = ssum[t] - s;
    for (int i = beg; i < end; i++) { g_rowptr[i] = run; run += g_deg_in[i]; }
    if (end == n) g_rowptr[n] = run;

    for (int i = beg; i < end; i++) {
        g_norm_in[i]  = rsqrtf((float)max(g_deg_in[i], 1));
        g_norm_out[i] = rsqrtf((float)max(g_deg_out[i], 1));
    }
}

// pre-convert W1 [F*96] and W2 [96*96] to tf32 bit patterns
__global__ void cvtw_kernel(const float* __restrict__ W1, const float* __restrict__ W2,
                            int n1, int n2) {
    int i = blockIdx.x * blockDim.x + threadIdx.x;
    if (i < n1) g_W1c[i] = __uint_as_float(f2tf32(W1[i]));
    else if (i < n1 + n2) g_W2c[i - n1] = __uint_as_float(f2tf32(W2[i - n1]));
}

__global__ void fill_kernel(const int* __restrict__ src, const int* __restrict__ dst,
                            const int* __restrict__ perm, int e) {
    int i = blockIdx.x * blockDim.x + threadIdx.x;
    if (i < e) {
        int d = dst[i];
        int s = src[i];
        int pos = g_rowptr[d] + atomicAdd(&g_fill[d], 1);
        g_col2[pos] = make_int2(s, perm[s]);
    }
}

// ---------------- tf32 mma.sync GEMM with 3-stage cp.async pipeline ------------------
// Ch[m][0..95] = half( rowscale[m]*(A[m,:K] @ B[K,96]) ); B pre-converted tf32 bits.
// CTA tile 128x96, 8 warps (4m x 2n), warp tile 32x48 (2x6 m16n8k8 atoms).
// A smem [r][36] (4g+t -> conflict-free), B smem [k][104] (8t+g -> conflict-free).
#define ASTR 36
#define BSTR 104
#define ABUF (128 * ASTR)              // 4608 floats
#define STAGEF (ABUF + 32 * BSTR)      // 7936 floats = 31744 B per stage
#define NSTAGE 3
__global__ __launch_bounds__(256) void gemm_mma_kernel(
    const float* __restrict__ A, int lda, int viewA,
    const float* __restrict__ B,
    __half* __restrict__ Ch, int ldc, int viewC,
    const float* __restrict__ rowscale,
    int M, int K, int cvtA)
{
    extern __shared__ float smf[];
    uint32_t sbase = smem_u32(smf);

    int tid = threadIdx.x;
    int wid = tid >> 5, lane = tid & 31;
    int g = lane >> 2, t = lane & 3;
    int wm = (wid & 3) * 32;        // warp m offset in tile
    int wn = (wid >> 2) * 48;       // warp n offset
    int row0 = blockIdx.x * 128;
    A += (size_t)blockIdx.y * viewA;
    Ch += (size_t)blockIdx.y * viewC;

    float acc[2][6][4];
    #pragma unroll
    for (int ma = 0; ma < 2; ma++)
        #pragma unroll
        for (int na = 0; na < 6; na++)
            #pragma unroll
            for (int c = 0; c < 4; c++) acc[ma][na][c] = 0.f;

    int qa = tid & 7;                 // float4 index within 32-k row
    int ra = tid >> 3;
    int nchunks = (K + 31) >> 5;

    auto load = [&](int i) {
        int k0 = i << 5;
        uint32_t st = sbase + (uint32_t)(i % NSTAGE) * (STAGEF * 4);
        #pragma unroll
        for (int j = 0; j < 4; j++) {
            int r = ra + 32 * j;
            int gr = row0 + r;
            int kc = k0 + 4 * qa;
            uint32_t ok = (gr < M && kc + 4 <= K) ? 16u : 0u;
            const float* gp = ok ? (A + (size_t)gr * lda + kc) : A;
            cpa16(st + (uint32_t)(r * ASTR + 4 * qa) * 4, gp, ok);
        }
        #pragma unroll
        for (int j = 0; j < 3; j++) {
            int idx = tid + j * 256;
            int kk = idx / 24, fc = idx - kk * 24;
            uint32_t ok = (k0 + kk < K) ? 16u : 0u;
            const float* gp = ok ? (B + (size_t)(k0 + kk) * HDIM + 4 * fc) : B;
            cpa16(st + (uint32_t)(ABUF + kk * BSTR + 4 * fc) * 4, gp, ok);
        }
    };

    load(0); CP_COMMIT();
    if (nchunks > 1) load(1);
    CP_COMMIT();

    for (int i = 0; i < nchunks; i++) {
        CP_WAIT1();
        __syncthreads();
        if (i + 2 < nchunks) load(i + 2);
        CP_COMMIT();

        const float* Asm = smf + (i % NSTAGE) * STAGEF;
        const float* Bsm = Asm + ABUF;
        #pragma unroll
        for (int ks = 0; ks < 4; ks++) {
            int k = ks * 8;
            uint32_t ar[2][4];
            #pragma unroll
            for (int ma = 0; ma < 2; ma++) {
                int rb = (wm + 16 * ma + g) * ASTR + k + t;
                ar[ma][0] = __float_as_uint(Asm[rb]);
                ar[ma][1] = __float_as_uint(Asm[rb + 8 * ASTR]);
                ar[ma][2] = __float_as_uint(Asm[rb + 4]);
                ar[ma][3] = __float_as_uint(Asm[rb + 8 * ASTR + 4]);
                if (cvtA) {
                    #pragma unroll
                    for (int u = 0; u < 4; u++)
                        ar[ma][u] = f2tf32(__uint_as_float(ar[ma][u]));
                }
            }
            int kb0 = (k + t) * BSTR, kb1 = (k + t + 4) * BSTR;
            #pragma unroll
            for (int na = 0; na < 6; na++) {
                int col = wn + 8 * na + g;
                uint32_t b0 = __float_as_uint(Bsm[kb0 + col]);
                uint32_t b1 = __float_as_uint(Bsm[kb1 + col]);
                mma_tf32(acc[0][na], ar[0], b0, b1);
                mma_tf32(acc[1][na], ar[1], b0, b1);
            }
        }
        __syncthreads();
    }

    // epilogue: write half2 (fp16 keeps tf32's 10-bit mantissa; range is safe here)
    #pragma unroll
    for (int ma = 0; ma < 2; ma++) {
        int r0 = row0 + wm + 16 * ma + g;
        int r1 = r0 + 8;
        float s0 = 1.f, s1 = 1.f;
        if (rowscale) {
            if (r0 < M) s0 = rowscale[r0];
            if (r1 < M) s1 = rowscale[r1];
        }
        #pragma unroll
        for (int na = 0; na < 6; na++) {
            int col = wn + 8 * na + 2 * t;
            if (r0 < M)
                *(__half2*)&Ch[(size_t)r0 * ldc + col] =
                    __floats2half2_rn(acc[ma][na][0] * s0, acc[ma][na][1] * s0);
            if (r1 < M)
                *(__half2*)&Ch[(size_t)r1 * ldc + col] =
                    __floats2half2_rn(acc[ma][na][2] * s1, acc[ma][na][3] * s1);
        }
    }
}

// ---------------- layer-1 aggregation: gathers Yh (fp16), dual view, half-warp each ----
// Writes P pre-rounded to tf32 bits so gemm2 needs no conversion.
__global__ __launch_bounds__(256) void spmm1_kernel(
    const __half* __restrict__ Yh, float* __restrict__ Pout,
    const float* __restrict__ b, const float* __restrict__ a, int n)
{
    int gw = (blockIdx.x * blockDim.x + threadIdx.x) >> 5;
    int lane = threadIdx.x & 31;
    if (gw >= n) return;
    int half_ = lane >> 4;       // 0: view1 (Y[s]), 1: view2 (Y[perm[s]])
    int l = lane & 15;

    int beg = g_rowptr[gw], end = g_rowptr[gw + 1];
    float2 acc0 = {0.f, 0.f}, acc1 = {0.f, 0.f}, acc2 = {0.f, 0.f};

    int e = beg;
    for (; e + 3 < end; e += 4) {
        int2 sp[4];
        #pragma unroll
        for (int q = 0; q < 4; q++) sp[q] = g_col2[e + q];
        float ns[4];
        #pragma unroll
        for (int q = 0; q < 4; q++) ns[q] = g_norm_out[sp[q].x];
        __half2 u[4][3];
        #pragma unroll
        for (int q = 0; q < 4; q++) {
            int s = half_ ? sp[q].y : sp[q].x;
            const __half2* h = (const __half2*)(Yh + (size_t)s * HDIM);
            u[q][0] = h[l]; u[q][1] = h[l + 16]; u[q][2] = h[l + 32];
        }
        #pragma unroll
        for (int q = 0; q < 4; q++) {
            float2 f0 = __half22float2(u[q][0]);
            float2 f1 = __half22float2(u[q][1]);
            float2 f2 = __half22float2(u[q][2]);
            acc0.x += ns[q] * f0.x; acc0.y += ns[q] * f0.y;
            acc1.x += ns[q] * f1.x; acc1.y += ns[q] * f1.y;
            acc2.x += ns[q] * f2.x; acc2.y += ns[q] * f2.y;
        }
    }
    for (; e < end; e++) {
        int2 sp0 = g_col2[e];
        float ns0 = g_norm_out[sp0.x];
        int s0 = half_ ? sp0.y : sp0.x;
        const __half2* h0 = (const __half2*)(Yh + (size_t)s0 * HDIM);
        float2 f0 = __half22float2(h0[l]);
        float2 f1 = __half22float2(h0[l + 16]);
        float2 f2 = __half22float2(h0[l + 32]);
        acc0.x += ns0 * f0.x; acc0.y += ns0 * f0.y;
        acc1.x += ns0 * f1.x; acc1.y += ns0 * f1.y;
        acc2.x += ns0 * f2.x; acc2.y += ns0 * f2.y;
    }

    float ni = g_norm_in[gw];
    float2* po = (float2*)(Pout + (size_t)gw * HDIM2);

    #pragma unroll
    for (int j = 0; j < 3; j++) {
        int idx = l + 16 * j;
        int c0 = 2 * idx;
        float2 acc = (j == 0) ? acc0 : (j == 1) ? acc1 : acc2;
        float h0 = acc.x * ni + b[c0];
        float h1 = acc.y * ni + b[c0 + 1];
        float z0 = (h0 >= 0.f) ? h0 : a[c0] * h0;
        float z1 = (h1 >= 0.f) ? h1 : a[c0 + 1] * h1;
        z0 = __uint_as_float(f2tf32(z0));
        z1 = __uint_as_float(f2tf32(z1));
        po[half_ * 48 + idx] = make_float2(z0, z1);
    }
}

// ---------------- layer-2 aggregation (fp16 gather) + PReLU + fused projection sum -----
__global__ __launch_bounds__(256) void spmm2_kernel(
    const __half* __restrict__ Hh,
    const float* __restrict__ b, const float* __restrict__ a,
    float* __restrict__ out, int n)
{
    int gw = (blockIdx.x * blockDim.x + threadIdx.x) >> 5;
    int lane = threadIdx.x & 31;
    if (gw >= n) return;

    int beg = g_rowptr[gw], end = g_rowptr[gw + 1];
    float2 acc0 = {0.f, 0.f}, acc1 = {0.f, 0.f}, acc2 = {0.f, 0.f};

    int e = beg;
    for (; e + 3 < end; e += 4) {
        __half2 u[4][3];
        #pragma unroll
        for (int q = 0; q < 4; q++) {
            const __half2* h = (const __half2*)(Hh + (size_t)g_col2[e + q].x * HDIM2);
            u[q][0] = h[lane]; u[q][1] = h[lane + 32]; u[q][2] = h[lane + 64];
        }
        #pragma unroll
        for (int q = 0; q < 4; q++) {
            float2 f0 = __half22float2(u[q][0]);
            float2 f1 = __half22float2(u[q][1]);
            float2 f2 = __half22float2(u[q][2]);
            acc0.x += f0.x; acc0.y += f0.y;
            acc1.x += f1.x; acc1.y += f1.y;
            acc2.x += f2.x; acc2.y += f2.y;
        }
    }
    for (; e < end; e++) {
        const __half2* h0 = (const __half2*)(Hh + (size_t)g_col2[e].x * HDIM2);
        float2 f0 = __half22float2(h0[lane]);
        float2 f1 = __half22float2(h0[lane + 32]);
        float2 f2 = __half22float2(h0[lane + 64]);
        acc0.x += f0.x; acc0.y += f0.y;
        acc1.x += f1.x; acc1.y += f1.y;
        acc2.x += f2.x; acc2.y += f2.y;
    }

    float ni = g_norm_in[gw];
    float s1 = 0.f, s2 = 0.f;

    #pragma unroll
    for (int j = 0; j < 3; j++) {
        int idx = lane + 32 * j;
        float2 acc = (j == 0) ? acc0 : (j == 1) ? acc1 : acc2;
        int v = idx >= 48;
        int c0 = 2 * idx - 96 * v;
        float h0 = acc.x * ni + b[c0];
        float h1 = acc.y * ni + b[c0 + 1];
        float z0 = (h0 >= 0.f) ? h0 : a[c0] * h0;
        float z1 = (h1 >= 0.f) ? h1 : a[c0 + 1] * h1;
        float contrib = z0 * g_wsum[c0] + z1 * g_wsum[c0 + 1];
        if (v) s2 += contrib; else s1 += contrib;
    }

    #pragma unroll
    for (int off = 16; off > 0; off >>= 1) {
        s1 += __shfl_xor_sync(0xffffffff, s1, off);
        s2 += __shfl_xor_sync(0xffffffff, s2, off);
    }
    if (lane == 0) {
        out[gw]     = s1 + g_bmsum;
        out[n + gw] = s2 + g_bmsum;
    }
}

// ---------------- launch ----------------
extern "C" void kernel_launch(void* const* d_in, const int* in_sizes, int n_in,
                              void* d_out, int out_size) {
    const float* x   = (const float*)d_in[0];
    const int*   src = (const int*)  d_in[1];
    const int*   dst = (const int*)  d_in[2];
    const int*   perm= (const int*)  d_in[3];
    const float* W1  = (const float*)d_in[4];
    const float* b1  = (const float*)d_in[5];
    const float* a1  = (const float*)d_in[6];
    const float* W2  = (const float*)d_in[7];
    const float* b2  = (const float*)d_in[8];
    const float* a2  = (const float*)d_in[9];
    const float* Wm  = (const float*)d_in[10];
    const float* bm  = (const float*)d_in[11];
    float* out = (float*)d_out;

    int E = in_sizes[1];
    int n = in_sizes[3];
    int F = in_sizes[0] / n;

    float *pP, *pNormOut, *pW1c, *pW2c;
    __half *pYh, *pHBh;
    int *pDegIn, *pDegOut, *pFill;
    cudaGetSymbolAddress((void**)&pYh, g_Yh);
    cudaGetSymbolAddress((void**)&pHBh, g_HBh);
    cudaGetSymbolAddress((void**)&pP, g_P);
    cudaGetSymbolAddress((void**)&pNormOut, g_norm_out);
    cudaGetSymbolAddress((void**)&pDegIn, g_deg_in);
    cudaGetSymbolAddress((void**)&pDegOut, g_deg_out);
    cudaGetSymbolAddress((void**)&pFill, g_fill);
    cudaGetSymbolAddress((void**)&pW1c, g_W1c);
    cudaGetSymbolAddress((void**)&pW2c, g_W2c);

    const int SMEM_BYTES = NSTAGE * STAGEF * 4;   // 95232
    static int inited = 0;
    if (!inited) {
        cudaFuncSetAttribute(gemm_mma_kernel,
                             cudaFuncAttributeMaxDynamicSharedMemorySize, SMEM_BYTES);
        inited = 1;
    }

    int nTiles = (n + 127) / 128;
    int nW = F * HDIM + HDIM * HDIM;

    cudaMemsetAsync(pDegIn, 0, n * sizeof(int));
    cudaMemsetAsync(pDegOut, 0, n * sizeof(int));
    cudaMemsetAsync(pFill, 0, n * sizeof(int));

    degree_kernel<<<(E + 255) / 256, 256>>>(src, dst, E);
    scan_kernel<<<1, 1024>>>(n, Wm, bm);
    cvtw_kernel<<<(nW + 255) / 256, 256>>>(W1, W2, F * HDIM, HDIM * HDIM);
    // Y = X @ W1c (tf32 mma.sync; fp16 output for gather)
    gemm_mma_kernel<<<dim3(nTiles, 1), 256, SMEM_BYTES>>>(
        x, F, 0, pW1c, pYh, HDIM, 0, nullptr, n, F, 1);
    fill_kernel<<<(E + 255) / 256, 256>>>(src, dst, perm, E);
    // layer-1 aggregation (dual view, fp16 gather) + PReLU, P tf32-rounded fp32
    spmm1_kernel<<<(n + 7) / 8, 256>>>(pYh, pP, b1, a1, n);
    // layer-2 GEMMs, both views via grid.y; fp16 output, norm_out fused
    gemm_mma_kernel<<<dim3(nTiles, 2), 256, SMEM_BYTES>>>(
        pP, HDIM2, HDIM, pW2c, pHBh, HDIM2, HDIM, pNormOut, n, HDIM, 0);
    // layer-2 aggregation (fp16 gather) + PReLU + fused projection row-sum
    spmm2_kernel<<<(n + 7) / 8, 256>>>(pHBh, b2, a2, out, n);
}

// round 13
// speedup vs baseline: 1.5223x; 1.5223x over previous
#include <cuda_runtime.h>
#include <cstdint>

#define MAXN 50000
#define MAXE 800000
#define HDIM 96
#define HDIM2 192
#define MAXF 512

// ---------------- scratch (device globals; no allocation allowed) ----------------
__device__ int   g_deg_in[MAXN];
__device__ int   g_deg_out[MAXN];
__device__ int   g_fill[MAXN];
__device__ int   g_rowptr[MAXN + 1];
__device__ int2  g_col2[MAXE];                 // {src, perm[src]} per edge (CSR by dst)
__device__ float g_norm_in[MAXN];
__device__ float g_norm_out[MAXN];
__device__ float g_Y[(size_t)MAXN * HDIM];     // x @ W1 (shared by both views)
__device__ float g_HB[(size_t)MAXN * HDIM2];   // layer-2 pre-aggregation features
__device__ float g_P[(size_t)MAXN * HDIM2];    // layer-1 post-PReLU, tf32-rounded
__device__ float g_W1c[MAXF * HDIM];           // W1 pre-converted to tf32 bits
__device__ float g_W2c[HDIM * HDIM];           // W2 pre-converted to tf32 bits
__device__ float g_wsum[HDIM];
__device__ float g_bmsum;

// ---------------- tf32 / cp.async helpers ----------------
__device__ __forceinline__ uint32_t f2tf32(float x) {
    uint32_t u;
    asm("cvt.rna.tf32.f32 %0, %1;" : "=r"(u) : "f"(x));
    return u;
}
__device__ __forceinline__ void mma_tf32(float* c, const uint32_t* a,
                                         uint32_t b0, uint32_t b1) {
    asm volatile(
        "mma.sync.aligned.m16n8k8.row.col.f32.tf32.tf32.f32 "
        "{%0,%1,%2,%3},{%4,%5,%6,%7},{%8,%9},{%0,%1,%2,%3};"
        : "+f"(c[0]), "+f"(c[1]), "+f"(c[2]), "+f"(c[3])
        : "r"(a[0]), "r"(a[1]), "r"(a[2]), "r"(a[3]), "r"(b0), "r"(b1));
}
__device__ __forceinline__ uint32_t smem_u32(const void* p) {
    uint32_t a;
    asm("{ .reg .u64 t; cvta.to.shared.u64 t, %1; cvt.u32.u64 %0, t; }" : "=r"(a) : "l"(p));
    return a;
}
// 16B async copy; sz=0 -> zero-fill destination
__device__ __forceinline__ void cpa16(uint32_t saddr, const void* gaddr, uint32_t sz) {
    asm volatile("cp.async.cg.shared.global [%0], [%1], 16, %2;"
                 :: "r"(saddr), "l"(gaddr), "r"(sz));
}
#define CP_COMMIT() asm volatile("cp.async.commit_group;" ::: "memory")
#define CP_WAIT1()  asm volatile("cp.async.wait_group 1;" ::: "memory")

// ---------------- small setup kernels ----------------
__global__ void degree_kernel(const int* __restrict__ src, const int* __restrict__ dst, int e) {
    int i = blockIdx.x * blockDim.x + threadIdx.x;
    if (i < e) {
        atomicAdd(&g_deg_out[src[i]], 1);
        atomicAdd(&g_deg_in[dst[i]], 1);
    }
}

__global__ void scan_kernel(int n, const float* __restrict__ Wm, const float* __restrict__ bm) {
    __shared__ int ssum[1024];
    int t = threadIdx.x;

    if (t < HDIM) {
        float s = 0.f;
        #pragma unroll 8
        for (int j = 0; j < HDIM; j++) s += Wm[t * HDIM + j];
        g_wsum[t] = s;
    }
    if (t == 0) {
        float s = 0.f;
        for (int j = 0; j < HDIM; j++) s += bm[j];
        g_bmsum = s;
    }

    int chunk = (n + 1023) / 1024;
    int beg = min(t * chunk, n);
    int end = min(beg + chunk, n);
    int s = 0;
    for (int i = beg; i < end; i++) s += g_deg_in[i];
    ssum[t] = s;
    __syncthreads();
    for (int off = 1; off < 1024; off <<= 1) {
        int v = (t >= off) ? ssum[t - off] : 0;
        __syncthreads();
        ssum[t] += v;
        __syncthreads();
    }
    int run = ssum[t] - s;
    for (int i = beg; i < end; i++) { g_rowptr[i] = run; run += g_deg_in[i]; }
    if (end == n) g_rowptr[n] = run;

    for (int i = beg; i < end; i++) {
        g_norm_in[i]  = rsqrtf((float)max(g_deg_in[i], 1));
        g_norm_out[i] = rsqrtf((float)max(g_deg_out[i], 1));
    }
}

// pre-convert W1 [F*96] and W2 [96*96] to tf32 bit patterns
__global__ void cvtw_kernel(const float* __restrict__ W1, const float* __restrict__ W2,
                            int n1, int n2) {
    int i = blockIdx.x * blockDim.x + threadIdx.x;
    if (i < n1) g_W1c[i] = __uint_as_float(f2tf32(W1[i]));
    else if (i < n1 + n2) g_W2c[i - n1] = __uint_as_float(f2tf32(W2[i - n1]));
}

__global__ void fill_kernel(const int* __restrict__ src, const int* __restrict__ dst,
                            const int* __restrict__ perm, int e) {
    int i = blockIdx.x * blockDim.x + threadIdx.x;
    if (i < e) {
        int d = dst[i];
        int s = src[i];
        int pos = g_rowptr[d] + atomicAdd(&g_fill[d], 1);
        g_col2[pos] = make_int2(s, perm[s]);
    }
}

// ---------------- tf32 mma.sync GEMM with 2-stage cp.async pipeline, 3 CTAs/SM --------
// C[m][0..95] = rowscale[m]*(A[m,:K] @ B[K,96]); B pre-converted tf32 bits.
// CTA tile 128x96, 8 warps (4m x 2n), warp tile 32x48 (2x6 m16n8k8 atoms).
// A smem [r][36] (4g+t -> conflict-free), B smem [k][104] (8t+g -> conflict-free).
#define ASTR 36
#define BSTR 104
#define ABUF (128 * ASTR)              // 4608 floats
#define STAGEF (ABUF + 32 * BSTR)      // 7936 floats = 31744 B per stage
#define NSTAGE 2
__global__ __launch_bounds__(256, 3) void gemm_mma_kernel(
    const float* __restrict__ A, int lda, int viewA,
    const float* __restrict__ B,
    float* __restrict__ C, int ldc, int viewC,
    const float* __restrict__ rowscale,
    int M, int K, int cvtA)
{
    extern __shared__ float smf[];
    uint32_t sbase = smem_u32(smf);

    int tid = threadIdx.x;
    int wid = tid >> 5, lane = tid & 31;
    int g = lane >> 2, t = lane & 3;
    int wm = (wid & 3) * 32;        // warp m offset in tile
    int wn = (wid >> 2) * 48;       // warp n offset
    int row0 = blockIdx.x * 128;
    A += (size_t)blockIdx.y * viewA;
    C += (size_t)blockIdx.y * viewC;

    float acc[2][6][4];
    #pragma unroll
    for (int ma = 0; ma < 2; ma++)
        #pragma unroll
        for (int na = 0; na < 6; na++)
            #pragma unroll
            for (int c = 0; c < 4; c++) acc[ma][na][c] = 0.f;

    int qa = tid & 7;                 // float4 index within 32-k row
    int ra = tid >> 3;
    int nchunks = (K + 31) >> 5;

    auto load = [&](int i) {
        int k0 = i << 5;
        uint32_t st = sbase + (uint32_t)(i & 1) * (STAGEF * 4);
        #pragma unroll
        for (int j = 0; j < 4; j++) {
            int r = ra + 32 * j;
            int gr = row0 + r;
            int kc = k0 + 4 * qa;
            uint32_t ok = (gr < M && kc + 4 <= K) ? 16u : 0u;
            const float* gp = ok ? (A + (size_t)gr * lda + kc) : A;
            cpa16(st + (uint32_t)(r * ASTR + 4 * qa) * 4, gp, ok);
        }
        #pragma unroll
        for (int j = 0; j < 3; j++) {
            int idx = tid + j * 256;
            int kk = idx / 24, fc = idx - kk * 24;
            uint32_t ok = (k0 + kk < K) ? 16u : 0u;
            const float* gp = ok ? (B + (size_t)(k0 + kk) * HDIM + 4 * fc) : B;
            cpa16(st + (uint32_t)(ABUF + kk * BSTR + 4 * fc) * 4, gp, ok);
        }
    };

    // prologue: both stages in flight
    load(0); CP_COMMIT();
    if (nchunks > 1) load(1);
    CP_COMMIT();

    for (int i = 0; i < nchunks; i++) {
        CP_WAIT1();              // stage i landed (next stage may still be in flight)
        __syncthreads();

        const float* Asm = smf + (i & 1) * STAGEF;
        const float* Bsm = Asm + ABUF;
        #pragma unroll
        for (int ks = 0; ks < 4; ks++) {
            int k = ks * 8;
            uint32_t ar[2][4];
            #pragma unroll
            for (int ma = 0; ma < 2; ma++) {
                int rb = (wm + 16 * ma + g) * ASTR + k + t;
                ar[ma][0] = __float_as_uint(Asm[rb]);
                ar[ma][1] = __float_as_uint(Asm[rb + 8 * ASTR]);
                ar[ma][2] = __float_as_uint(Asm[rb + 4]);
                ar[ma][3] = __float_as_uint(Asm[rb + 8 * ASTR + 4]);
                if (cvtA) {
                    #pragma unroll
                    for (int u = 0; u < 4; u++)
                        ar[ma][u] = f2tf32(__uint_as_float(ar[ma][u]));
                }
            }
            int kb0 = (k + t) * BSTR, kb1 = (k + t + 4) * BSTR;
            #pragma unroll
            for (int na = 0; na < 6; na++) {
                int col = wn + 8 * na + g;
                uint32_t b0 = __float_as_uint(Bsm[kb0 + col]);
                uint32_t b1 = __float_as_uint(Bsm[kb1 + col]);
                mma_tf32(acc[0][na], ar[0], b0, b1);
                mma_tf32(acc[1][na], ar[1], b0, b1);
            }
        }
        __syncthreads();         // buffer (i&1) free for reuse
        if (i + 2 < nchunks) load(i + 2);
        CP_COMMIT();             // one commit per iteration keeps group accounting aligned
    }

    #pragma unroll
    for (int ma = 0; ma < 2; ma++) {
        int r0 = row0 + wm + 16 * ma + g;
        int r1 = r0 + 8;
        float s0 = 1.f, s1 = 1.f;
        if (rowscale) {
            if (r0 < M) s0 = rowscale[r0];
            if (r1 < M) s1 = rowscale[r1];
        }
        #pragma unroll
        for (int na = 0; na < 6; na++) {
            int col = wn + 8 * na + 2 * t;
            if (r0 < M) {
                float2 v = make_float2(acc[ma][na][0] * s0, acc[ma][na][1] * s0);
                *(float2*)&C[(size_t)r0 * ldc + col] = v;
            }
            if (r1 < M) {
                float2 v = make_float2(acc[ma][na][2] * s1, acc[ma][na][3] * s1);
                *(float2*)&C[(size_t)r1 * ldc + col] = v;
            }
        }
    }
}

// ---------------- layer-1 aggregation: gathers Y directly (dual view, half-warp each) --
// Writes P pre-rounded to tf32 bits so gemm2 needs no conversion.
__global__ __launch_bounds__(256) void spmm1_kernel(
    const float* __restrict__ Y, float* __restrict__ Pout,
    const float* __restrict__ b, const float* __restrict__ a, int n)
{
    int gw = (blockIdx.x * blockDim.x + threadIdx.x) >> 5;
    int lane = threadIdx.x & 31;
    if (gw >= n) return;
    int half = lane >> 4;        // 0: view1 (Y[s]), 1: view2 (Y[perm[s]])
    int l = lane & 15;

    int beg = g_rowptr[gw], end = g_rowptr[gw + 1];
    float2 acc0 = {0.f, 0.f}, acc1 = {0.f, 0.f}, acc2 = {0.f, 0.f};

    int e = beg;
    for (; e + 3 < end; e += 4) {
        int2 sp[4];
        #pragma unroll
        for (int q = 0; q < 4; q++) sp[q] = g_col2[e + q];
        float ns[4];
        #pragma unroll
        for (int q = 0; q < 4; q++) ns[q] = g_norm_out[sp[q].x];
        float2 u[4][3];
        #pragma unroll
        for (int q = 0; q < 4; q++) {
            int s = half ? sp[q].y : sp[q].x;
            const float2* h = (const float2*)(Y + (size_t)s * HDIM);
            u[q][0] = h[l]; u[q][1] = h[l + 16]; u[q][2] = h[l + 32];
        }
        #pragma unroll
        for (int q = 0; q < 4; q++) {
            acc0.x += ns[q] * u[q][0].x; acc0.y += ns[q] * u[q][0].y;
            acc1.x += ns[q] * u[q][1].x; acc1.y += ns[q] * u[q][1].y;
            acc2.x += ns[q] * u[q][2].x; acc2.y += ns[q] * u[q][2].y;
        }
    }
    for (; e < end; e++) {
        int2 sp0 = g_col2[e];
        float ns0 = g_norm_out[sp0.x];
        int s0 = half ? sp0.y : sp0.x;
        const float2* h0 = (const float2*)(Y + (size_t)s0 * HDIM);
        float2 u0 = h0[l], u1 = h0[l + 16], u2 = h0[l + 32];
        acc0.x += ns0 * u0.x; acc0.y += ns0 * u0.y;
        acc1.x += ns0 * u1.x; acc1.y += ns0 * u1.y;
        acc2.x += ns0 * u2.x; acc2.y += ns0 * u2.y;
    }

    float ni = g_norm_in[gw];
    float2* po = (float2*)(Pout + (size_t)gw * HDIM2);

    #pragma unroll
    for (int j = 0; j < 3; j++) {
        int idx = l + 16 * j;
        int c0 = 2 * idx;
        float2 acc = (j == 0) ? acc0 : (j == 1) ? acc1 : acc2;
        float h0 = acc.x * ni + b[c0];
        float h1 = acc.y * ni + b[c0 + 1];
        float z0 = (h0 >= 0.f) ? h0 : a[c0] * h0;
        float z1 = (h1 >= 0.f) ? h1 : a[c0 + 1] * h1;
        z0 = __uint_as_float(f2tf32(z0));
        z1 = __uint_as_float(f2tf32(z1));
        po[half * 48 + idx] = make_float2(z0, z1);
    }
}

// ---------------- layer-2 aggregation + PReLU + fused projection row-sum ---------------
__global__ __launch_bounds__(256) void spmm2_kernel(
    const float* __restrict__ Hin,
    const float* __restrict__ b, const float* __restrict__ a,
    float* __restrict__ out, int n)
{
    int gw = (blockIdx.x * blockDim.x + threadIdx.x) >> 5;
    int lane = threadIdx.x & 31;
    if (gw >= n) return;

    int beg = g_rowptr[gw], end = g_rowptr[gw + 1];
    float2 acc0 = {0.f, 0.f}, acc1 = {0.f, 0.f}, acc2 = {0.f, 0.f};

    int e = beg;
    for (; e + 3 < end; e += 4) {
        float2 u[4][3];
        #pragma unroll
        for (int q = 0; q < 4; q++) {
            const float2* h = (const float2*)(Hin + (size_t)g_col2[e + q].x * HDIM2);
            u[q][0] = h[lane]; u[q][1] = h[lane + 32]; u[q][2] = h[lane + 64];
        }
        #pragma unroll
        for (int q = 0; q < 4; q++) {
            acc0.x += u[q][0].x; acc0.y += u[q][0].y;
            acc1.x += u[q][1].x; acc1.y += u[q][1].y;
            acc2.x += u[q][2].x; acc2.y += u[q][2].y;
        }
    }
    for (; e < end; e++) {
        const float2* h0 = (const float2*)(Hin + (size_t)g_col2[e].x * HDIM2);
        float2 u0 = h0[lane], u1 = h0[lane + 32], u2 = h0[lane + 64];
        acc0.x += u0.x; acc0.y += u0.y;
        acc1.x += u1.x; acc1.y += u1.y;
        acc2.x += u2.x; acc2.y += u2.y;
    }

    float ni = g_norm_in[gw];
    float s1 = 0.f, s2 = 0.f;

    #pragma unroll
    for (int j = 0; j < 3; j++) {
        int idx = lane + 32 * j;
        float2 acc = (j == 0) ? acc0 : (j == 1) ? acc1 : acc2;
        int v = idx >= 48;
        int c0 = 2 * idx - 96 * v;
        float h0 = acc.x * ni + b[c0];
        float h1 = acc.y * ni + b[c0 + 1];
        float z0 = (h0 >= 0.f) ? h0 : a[c0] * h0;
        float z1 = (h1 >= 0.f) ? h1 : a[c0 + 1] * h1;
        float contrib = z0 * g_wsum[c0] + z1 * g_wsum[c0 + 1];
        if (v) s2 += contrib; else s1 += contrib;
    }

    #pragma unroll
    for (int off = 16; off > 0; off >>= 1) {
        s1 += __shfl_xor_sync(0xffffffff, s1, off);
        s2 += __shfl_xor_sync(0xffffffff, s2, off);
    }
    if (lane == 0) {
        out[gw]     = s1 + g_bmsum;
        out[n + gw] = s2 + g_bmsum;
    }
}

// ---------------- launch ----------------
extern "C" void kernel_launch(void* const* d_in, const int* in_sizes, int n_in,
                              void* d_out, int out_size) {
    const float* x   = (const float*)d_in[0];
    const int*   src = (const int*)  d_in[1];
    const int*   dst = (const int*)  d_in[2];
    const int*   perm= (const int*)  d_in[3];
    const float* W1  = (const float*)d_in[4];
    const float* b1  = (const float*)d_in[5];
    const float* a1  = (const float*)d_in[6];
    const float* W2  = (const float*)d_in[7];
    const float* b2  = (const float*)d_in[8];
    const float* a2  = (const float*)d_in[9];
    const float* Wm  = (const float*)d_in[10];
    const float* bm  = (const float*)d_in[11];
    float* out = (float*)d_out;

    int E = in_sizes[1];
    int n = in_sizes[3];
    int F = in_sizes[0] / n;

    float *pY, *pHB, *pP, *pNormOut, *pW1c, *pW2c;
    int *pDegIn, *pDegOut, *pFill;
    cudaGetSymbolAddress((void**)&pY, g_Y);
    cudaGetSymbolAddress((void**)&pHB, g_HB);
    cudaGetSymbolAddress((void**)&pP, g_P);
    cudaGetSymbolAddress((void**)&pNormOut, g_norm_out);
    cudaGetSymbolAddress((void**)&pDegIn, g_deg_in);
    cudaGetSymbolAddress((void**)&pDegOut, g_deg_out);
    cudaGetSymbolAddress((void**)&pFill, g_fill);
    cudaGetSymbolAddress((void**)&pW1c, g_W1c);
    cudaGetSymbolAddress((void**)&pW2c, g_W2c);

    const int SMEM_BYTES = NSTAGE * STAGEF * 4;   // 63488
    static int inited = 0;
    if (!inited) {
        cudaFuncSetAttribute(gemm_mma_kernel,
                             cudaFuncAttributeMaxDynamicSharedMemorySize, SMEM_BYTES);
        inited = 1;
    }

    int nTiles = (n + 127) / 128;
    int nW = F * HDIM + HDIM * HDIM;

    cudaMemsetAsync(pDegIn, 0, n * sizeof(int));
    cudaMemsetAsync(pDegOut, 0, n * sizeof(int));
    cudaMemsetAsync(pFill, 0, n * sizeof(int));

    degree_kernel<<<(E + 255) / 256, 256>>>(src, dst, E);
    scan_kernel<<<1, 1024>>>(n, Wm, bm);
    cvtw_kernel<<<(nW + 255) / 256, 256>>>(W1, W2, F * HDIM, HDIM * HDIM);
    // Y = X @ W1c (tf32 mma.sync; A converted at fragment load)
    gemm_mma_kernel<<<dim3(nTiles, 1), 256, SMEM_BYTES>>>(
        x, F, 0, pW1c, pY, HDIM, 0, nullptr, n, F, 1);
    fill_kernel<<<(E + 255) / 256, 256>>>(src, dst, perm, E);
    // layer-1 aggregation (dual view) + PReLU, P pre-rounded to tf32
    spmm1_kernel<<<(n + 7) / 8, 256>>>(pY, pP, b1, a1, n);
    // layer-2 GEMMs, both views via grid.y; no conversions needed
    gemm_mma_kernel<<<dim3(nTiles, 2), 256, SMEM_BYTES>>>(
        pP, HDIM2, HDIM, pW2c, pHB, HDIM2, HDIM, pNormOut, n, HDIM, 0);
    // layer-2 aggregation + PReLU + fused projection row-sum
    spmm2_kernel<<<(n + 7) / 8, 256>>>(pHB, b2, a2, out, n);
}

// round 15
// speedup vs baseline: 1.5483x; 1.0171x over previous
#include <cuda_runtime.h>
#include <cuda_fp16.h>
#include <cstdint>

#define MAXN 50000
#define MAXE 800000
#define HDIM 96
#define HDIM2 192
#define MAXF 512

// ---------------- scratch (device globals; no allocation allowed) ----------------
__device__ int    g_cnt[3 * MAXN];              // [deg_in | deg_out | fill], one memset
__device__ int    g_rowptr[MAXN + 1];
__device__ int2   g_col2[MAXE];                 // {src, perm[src]} per edge (CSR by dst)
__device__ float  g_norm_in[MAXN];
__device__ float  g_norm_out[MAXN];
__device__ float  g_Y[(size_t)MAXN * HDIM];     // x @ W1, fp32 (gemm1 output)
__device__ float  g_HB[(size_t)MAXN * HDIM2];   // layer-2 features, fp32 (gemm2 output)
__device__ __half g_Yh[(size_t)MAXN * HDIM];    // fp16 mirror for gather
__device__ __half g_HBh[(size_t)MAXN * HDIM2];  // fp16 mirror for gather
__device__ float  g_P[(size_t)MAXN * HDIM2];    // layer-1 post-PReLU, tf32-rounded
__device__ float  g_W1c[MAXF * HDIM];           // W1 pre-converted to tf32 bits
__device__ float  g_W2c[HDIM * HDIM];           // W2 pre-converted to tf32 bits
__device__ float  g_wsum[HDIM];
__device__ float  g_bmsum;

#define DEG_IN  (g_cnt)
#define DEG_OUT (g_cnt + MAXN)
#define FILLC   (g_cnt + 2 * MAXN)

// ---------------- tf32 / cp.async helpers ----------------
__device__ __forceinline__ uint32_t f2tf32(float x) {
    uint32_t u;
    asm("cvt.rna.tf32.f32 %0, %1;" : "=r"(u) : "f"(x));
    return u;
}
__device__ __forceinline__ uint32_t h2_bits(__half2 h) {
    return *reinterpret_cast<uint32_t*>(&h);
}
__device__ __forceinline__ void mma_tf32(float* c, const uint32_t* a,
                                         uint32_t b0, uint32_t b1) {
    asm volatile(
        "mma.sync.aligned.m16n8k8.row.col.f32.tf32.tf32.f32 "
        "{%0,%1,%2,%3},{%4,%5,%6,%7},{%8,%9},{%0,%1,%2,%3};"
        : "+f"(c[0]), "+f"(c[1]), "+f"(c[2]), "+f"(c[3])
        : "r"(a[0]), "r"(a[1]), "r"(a[2]), "r"(a[3]), "r"(b0), "r"(b1));
}
__device__ __forceinline__ uint32_t smem_u32(const void* p) {
    uint32_t a;
    asm("{ .reg .u64 t; cvta.to.shared.u64 t, %1; cvt.u32.u64 %0, t; }" : "=r"(a) : "l"(p));
    return a;
}
// 16B async copy; sz=0 -> zero-fill destination
__device__ __forceinline__ void cpa16(uint32_t saddr, const void* gaddr, uint32_t sz) {
    asm volatile("cp.async.cg.shared.global [%0], [%1], 16, %2;"
                 :: "r"(saddr), "l"(gaddr), "r"(sz));
}
#define CP_COMMIT() asm volatile("cp.async.commit_group;" ::: "memory")
#define CP_WAIT1()  asm volatile("cp.async.wait_group 1;" ::: "memory")

// ---------------- small setup kernels ----------------
__global__ void degree_kernel(const int* __restrict__ src, const int* __restrict__ dst, int e) {
    int i = blockIdx.x * blockDim.x + threadIdx.x;
    if (i < e) {
        atomicAdd(&DEG_OUT[src[i]], 1);
        atomicAdd(&DEG_IN[dst[i]], 1);
    }
}

__global__ void scan_kernel(int n, const float* __restrict__ Wm, const float* __restrict__ bm) {
    __shared__ int ssum[1024];
    int t = threadIdx.x;

    if (t < HDIM) {
        float s = 0.f;
        #pragma unroll 8
        for (int j = 0; j < HDIM; j++) s += Wm[t * HDIM + j];
        g_wsum[t] = s;
    }
    if (t == 0) {
        float s = 0.f;
        for (int j = 0; j < HDIM; j++) s += bm[j];
        g_bmsum = s;
    }

    int chunk = (n + 1023) / 1024;
    int beg = min(t * chunk, n);
    int end = min(beg + chunk, n);
    int s = 0;
    for (int i = beg; i < end; i++) s += DEG_IN[i];
    ssum[t] = s;
    __syncthreads();
    for (int off = 1; off < 1024; off <<= 1) {
        int v = (t >= off) ? ssum[t - off] : 0;
        __syncthreads();
        ssum[t] += v;
        __syncthreads();
    }
    int run = ssum[t] - s;
    for (int i = beg; i < end; i++) { g_rowptr[i] = run; run += DEG_IN[i]; }
    if (end == n) g_rowptr[n] = run;

    for (int i = beg; i < end; i++) {
        g_norm_in[i]  = rsqrtf((float)max(DEG_IN[i], 1));
        g_norm_out[i] = rsqrtf((float)max(DEG_OUT[i], 1));
    }
}

// pre-convert W1 [F*96] and W2 [96*96] to tf32 bit patterns
__global__ void cvtw_kernel(const float* __restrict__ W1, const float* __restrict__ W2,
                            int n1, int n2) {
    int i = blockIdx.x * blockDim.x + threadIdx.x;
    if (i < n1) g_W1c[i] = __uint_as_float(f2tf32(W1[i]));
    else if (i < n1 + n2) g_W2c[i - n1] = __uint_as_float(f2tf32(W2[i - n1]));
}

__global__ void fill_kernel(const int* __restrict__ src, const int* __restrict__ dst,
                            const int* __restrict__ perm, int e) {
    int i = blockIdx.x * blockDim.x + threadIdx.x;
    if (i < e) {
        int d = dst[i];
        int s = src[i];
        int pos = g_rowptr[d] + atomicAdd(&FILLC[d], 1);
        g_col2[pos] = make_int2(s, perm[s]);
    }
}

// fp32 -> fp16 mirror, fully coalesced (8 floats in, 16B out per thread)
__global__ void cvth_kernel(const float4* __restrict__ in, uint4* __restrict__ out, int n8) {
    int i = blockIdx.x * blockDim.x + threadIdx.x;
    if (i < n8) {
        float4 a = in[2 * i], b = in[2 * i + 1];
        uint4 o;
        o.x = h2_bits(__floats2half2_rn(a.x, a.y));
        o.y = h2_bits(__floats2half2_rn(a.z, a.w));
        o.z = h2_bits(__floats2half2_rn(b.x, b.y));
        o.w = h2_bits(__floats2half2_rn(b.z, b.w));
        out[i] = o;
    }
}

// ---------------- tf32 mma.sync GEMM with 2-stage cp.async pipeline, 3 CTAs/SM --------
// C[m][0..95] = rowscale[m]*(A[m,:K] @ B[K,96]); B pre-converted tf32 bits.
// CTA tile 128x96, 8 warps (4m x 2n), warp tile 32x48 (2x6 m16n8k8 atoms).
#define ASTR 36
#define BSTR 104
#define ABUF (128 * ASTR)              // 4608 floats
#define STAGEF (ABUF + 32 * BSTR)      // 7936 floats = 31744 B per stage
#define NSTAGE 2
__global__ __launch_bounds__(256, 3) void gemm_mma_kernel(
    const float* __restrict__ A, int lda, int viewA,
    const float* __restrict__ B,
    float* __restrict__ C, int ldc, int viewC,
    const float* __restrict__ rowscale,
    int M, int K, int cvtA)
{
    extern __shared__ float smf[];
    uint32_t sbase = smem_u32(smf);

    int tid = threadIdx.x;
    int wid = tid >> 5, lane = tid & 31;
    int g = lane >> 2, t = lane & 3;
    int wm = (wid & 3) * 32;
    int wn = (wid >> 2) * 48;
    int row0 = blockIdx.x * 128;
    A += (size_t)blockIdx.y * viewA;
    C += (size_t)blockIdx.y * viewC;

    float acc[2][6][4];
    #pragma unroll
    for (int ma = 0; ma < 2; ma++)
        #pragma unroll
        for (int na = 0; na < 6; na++)
            #pragma unroll
            for (int c = 0; c < 4; c++) acc[ma][na][c] = 0.f;

    int qa = tid & 7;
    int ra = tid >> 3;
    int nchunks = (K + 31) >> 5;

    auto load = [&](int i) {
        int k0 = i << 5;
        uint32_t st = sbase + (uint32_t)(i & 1) * (STAGEF * 4);
        #pragma unroll
        for (int j = 0; j < 4; j++) {
            int r = ra + 32 * j;
            int gr = row0 + r;
            int kc = k0 + 4 * qa;
            uint32_t ok = (gr < M && kc + 4 <= K) ? 16u : 0u;
            const float* gp = ok ? (A + (size_t)gr * lda + kc) : A;
            cpa16(st + (uint32_t)(r * ASTR + 4 * qa) * 4, gp, ok);
        }
        #pragma unroll
        for (int j = 0; j < 3; j++) {
            int idx = tid + j * 256;
            int kk = idx / 24, fc = idx - kk * 24;
            uint32_t ok = (k0 + kk < K) ? 16u : 0u;
            const float* gp = ok ? (B + (size_t)(k0 + kk) * HDIM + 4 * fc) : B;
            cpa16(st + (uint32_t)(ABUF + kk * BSTR + 4 * fc) * 4, gp, ok);
        }
    };

    load(0); CP_COMMIT();
    if (nchunks > 1) load(1);
    CP_COMMIT();

    for (int i = 0; i < nchunks; i++) {
        CP_WAIT1();
        __syncthreads();

        const float* Asm = smf + (i & 1) * STAGEF;
        const float* Bsm = Asm + ABUF;
        #pragma unroll
        for (int ks = 0; ks < 4; ks++) {
            int k = ks * 8;
            uint32_t ar[2][4];
            #pragma unroll
            for (int ma = 0; ma < 2; ma++) {
                int rb = (wm + 16 * ma + g) * ASTR + k + t;
                ar[ma][0] = __float_as_uint(Asm[rb]);
                ar[ma][1] = __float_as_uint(Asm[rb + 8 * ASTR]);
                ar[ma][2] = __float_as_uint(Asm[rb + 4]);
                ar[ma][3] = __float_as_uint(Asm[rb + 8 * ASTR + 4]);
                if (cvtA) {
                    #pragma unroll
                    for (int u = 0; u < 4; u++)
                        ar[ma][u] = f2tf32(__uint_as_float(ar[ma][u]));
                }
            }
            int kb0 = (k + t) * BSTR, kb1 = (k + t + 4) * BSTR;
            #pragma unroll
            for (int na = 0; na < 6; na++) {
                int col = wn + 8 * na + g;
                uint32_t b0 = __float_as_uint(Bsm[kb0 + col]);
                uint32_t b1 = __float_as_uint(Bsm[kb1 + col]);
                mma_tf32(acc[0][na], ar[0], b0, b1);
                mma_tf32(acc[1][na], ar[1], b0, b1);
            }
        }
        __syncthreads();
        if (i + 2 < nchunks) load(i + 2);
        CP_COMMIT();
    }

    #pragma unroll
    for (int ma = 0; ma < 2; ma++) {
        int r0 = row0 + wm + 16 * ma + g;
        int r1 = r0 + 8;
        float s0 = 1.f, s1 = 1.f;
        if (rowscale) {
            if (r0 < M) s0 = rowscale[r0];
            if (r1 < M) s1 = rowscale[r1];
        }
        #pragma unroll
        for (int na = 0; na < 6; na++) {
            int col = wn + 8 * na + 2 * t;
            if (r0 < M) {
                float2 v = make_float2(acc[ma][na][0] * s0, acc[ma][na][1] * s0);
                *(float2*)&C[(size_t)r0 * ldc + col] = v;
            }
            if (r1 < M) {
                float2 v = make_float2(acc[ma][na][2] * s1, acc[ma][na][3] * s1);
                *(float2*)&C[(size_t)r1 * ldc + col] = v;
            }
        }
    }
}

// ---------------- layer-1 aggregation: gathers Yh (fp16), dual view, half-warp each ----
// Writes P pre-rounded to tf32 bits so gemm2 needs no conversion.
__global__ __launch_bounds__(256) void spmm1_kernel(
    const __half* __restrict__ Yh, float* __restrict__ Pout,
    const float* __restrict__ b, const float* __restrict__ a, int n)
{
    int gw = (blockIdx.x * blockDim.x + threadIdx.x) >> 5;
    int lane = threadIdx.x & 31;
    if (gw >= n) return;
    int hv = lane >> 4;          // 0: view1 (Y[s]), 1: view2 (Y[perm[s]])
    int l = lane & 15;

    int beg = g_rowptr[gw], end = g_rowptr[gw + 1];
    float2 acc0 = {0.f, 0.f}, acc1 = {0.f, 0.f}, acc2 = {0.f, 0.f};

    int e = beg;
    for (; e + 3 < end; e += 4) {
        int2 sp[4];
        #pragma unroll
        for (int q = 0; q < 4; q++) sp[q] = g_col2[e + q];
        float ns[4];
        #pragma unroll
        for (int q = 0; q < 4; q++) ns[q] = g_norm_out[sp[q].x];
        __half2 u[4][3];
        #pragma unroll
        for (int q = 0; q < 4; q++) {
            int s = hv ? sp[q].y : sp[q].x;
            const __half2* h = (const __half2*)(Yh + (size_t)s * HDIM);
            u[q][0] = h[l]; u[q][1] = h[l + 16]; u[q][2] = h[l + 32];
        }
        #pragma unroll
        for (int q = 0; q < 4; q++) {
            float2 f0 = __half22float2(u[q][0]);
            float2 f1 = __half22float2(u[q][1]);
            float2 f2 = __half22float2(u[q][2]);
            acc0.x += ns[q] * f0.x; acc0.y += ns[q] * f0.y;
            acc1.x += ns[q] * f1.x; acc1.y += ns[q] * f1.y;
            acc2.x += ns[q] * f2.x; acc2.y += ns[q] * f2.y;
        }
    }
    for (; e < end; e++) {
        int2 sp0 = g_col2[e];
        float ns0 = g_norm_out[sp0.x];
        int s0 = hv ? sp0.y : sp0.x;
        const __half2* h0 = (const __half2*)(Yh + (size_t)s0 * HDIM);
        float2 f0 = __half22float2(h0[l]);
        float2 f1 = __half22float2(h0[l + 16]);
        float2 f2 = __half22float2(h0[l + 32]);
        acc0.x += ns0 * f0.x; acc0.y += ns0 * f0.y;
        acc1.x += ns0 * f1.x; acc1.y += ns0 * f1.y;
        acc2.x += ns0 * f2.x; acc2.y += ns0 * f2.y;
    }

    float ni = g_norm_in[gw];
    float2* po = (float2*)(Pout + (size_t)gw * HDIM2);

    #pragma unroll
    for (int j = 0; j < 3; j++) {
        int idx = l + 16 * j;
        int c0 = 2 * idx;
        float2 acc = (j == 0) ? acc0 : (j == 1) ? acc1 : acc2;
        float h0 = acc.x * ni + b[c0];
        float h1 = acc.y * ni + b[c0 + 1];
        float z0 = (h0 >= 0.f) ? h0 : a[c0] * h0;
        float z1 = (h1 >= 0.f) ? h1 : a[c0 + 1] * h1;
        z0 = __uint_as_float(f2tf32(z0));
        z1 = __uint_as_float(f2tf32(z1));
        po[hv * 48 + idx] = make_float2(z0, z1);
    }
}

// ---------------- layer-2 aggregation (fp16 gather) + PReLU + fused projection sum -----
__global__ __launch_bounds__(256) void spmm2_kernel(
    const __half* __restrict__ Hh,
    const float* __restrict__ b, const float* __restrict__ a,
    float* __restrict__ out, int n)
{
    int gw = (blockIdx.x * blockDim.x + threadIdx.x) >> 5;
    int lane = threadIdx.x & 31;
    if (gw >= n) return;

    int beg = g_rowptr[gw], end = g_rowptr[gw + 1];
    float2 acc0 = {0.f, 0.f}, acc1 = {0.f, 0.f}, acc2 = {0.f, 0.f};

    int e = beg;
    for (; e + 3 < end; e += 4) {
        __half2 u[4][3];
        #pragma unroll
        for (int q = 0; q < 4; q++) {
            const __half2* h = (const __half2*)(Hh + (size_t)g_col2[e + q].x * HDIM2);
            u[q][0] = h[lane]; u[q][1] = h[lane + 32]; u[q][2] = h[lane + 64];
        }
        #pragma unroll
        for (int q = 0; q < 4; q++) {
            float2 f0 = __half22float2(u[q][0]);
            float2 f1 = __half22float2(u[q][1]);
            float2 f2 = __half22float2(u[q][2]);
            acc0.x += f0.x; acc0.y += f0.y;
            acc1.x += f1.x; acc1.y += f1.y;
            acc2.x += f2.x; acc2.y += f2.y;
        }
    }
    for (; e < end; e++) {
        const __half2* h0 = (const __half2*)(Hh + (size_t)g_col2[e].x * HDIM2);
        float2 f0 = __half22float2(h0[lane]);
        float2 f1 = __half22float2(h0[lane + 32]);
        float2 f2 = __half22float2(h0[lane + 64]);
        acc0.x += f0.x; acc0.y += f0.y;
        acc1.x += f1.x; acc1.y += f1.y;
        acc2.x += f2.x; acc2.y += f2.y;
    }

    float ni = g_norm_in[gw];
    float s1 = 0.f, s2 = 0.f;

    #pragma unroll
    for (int j = 0; j < 3; j++) {
        int idx = lane + 32 * j;
        float2 acc = (j == 0) ? acc0 : (j == 1) ? acc1 : acc2;
        int v = idx >= 48;
        int c0 = 2 * idx - 96 * v;
        float h0 = acc.x * ni + b[c0];
        float h1 = acc.y * ni + b[c0 + 1];
        float z0 = (h0 >= 0.f) ? h0 : a[c0] * h0;
        float z1 = (h1 >= 0.f) ? h1 : a[c0 + 1] * h1;
        float contrib = z0 * g_wsum[c0] + z1 * g_wsum[c0 + 1];
        if (v) s2 += contrib; else s1 += contrib;
    }

    #pragma unroll
    for (int off = 16; off > 0; off >>= 1) {
        s1 += __shfl_xor_sync(0xffffffff, s1, off);
        s2 += __shfl_xor_sync(0xffffffff, s2, off);
    }
    if (lane == 0) {
        out[gw]     = s1 + g_bmsum;
        out[n + gw] = s2 + g_bmsum;
    }
}

// ---------------- launch ----------------
extern "C" void kernel_launch(void* const* d_in, const int* in_sizes, int n_in,
                              void* d_out, int out_size) {
    const float* x   = (const float*)d_in[0];
    const int*   src = (const int*)  d_in[1];
    const int*   dst = (const int*)  d_in[2];
    const int*   perm= (const int*)  d_in[3];
    const float* W1  = (const float*)d_in[4];
    const float* b1  = (const float*)d_in[5];
    const float* a1  = (const float*)d_in[6];
    const float* W2  = (const float*)d_in[7];
    const float* b2  = (const float*)d_in[8];
    const float* a2  = (const float*)d_in[9];
    const float* Wm  = (const float*)d_in[10];
    const float* bm  = (const float*)d_in[11];
    float* out = (float*)d_out;

    int E = in_sizes[1];
    int n = in_sizes[3];
    int F = in_sizes[0] / n;

    float *pY, *pHB, *pP, *pNormOut, *pW1c, *pW2c;
    __half *pYh, *pHBh;
    int *pCnt;
    cudaGetSymbolAddress((void**)&pY, g_Y);
    cudaGetSymbolAddress((void**)&pHB, g_HB);
    cudaGetSymbolAddress((void**)&pYh, g_Yh);
    cudaGetSymbolAddress((void**)&pHBh, g_HBh);
    cudaGetSymbolAddress((void**)&pP, g_P);
    cudaGetSymbolAddress((void**)&pNormOut, g_norm_out);
    cudaGetSymbolAddress((void**)&pCnt, g_cnt);
    cudaGetSymbolAddress((void**)&pW1c, g_W1c);
    cudaGetSymbolAddress((void**)&pW2c, g_W2c);

    const int SMEM_BYTES = NSTAGE * STAGEF * 4;   // 63488
    static int inited = 0;
    if (!inited) {
        cudaFuncSetAttribute(gemm_mma_kernel,
                             cudaFuncAttributeMaxDynamicSharedMemorySize, SMEM_BYTES);
        inited = 1;
    }

    int nTiles = (n + 127) / 128;
    int nW = F * HDIM + HDIM * HDIM;

    cudaMemsetAsync(pCnt, 0, 3 * MAXN * sizeof(int));

    degree_kernel<<<(E + 255) / 256, 256>>>(src, dst, E);
    scan_kernel<<<1, 1024>>>(n, Wm, bm);
    cvtw_kernel<<<(nW + 255) / 256, 256>>>(W1, W2, F * HDIM, HDIM * HDIM);
    // Y = X @ W1c (tf32 mma.sync; fp32 output, unchanged from R13)
    gemm_mma_kernel<<<dim3(nTiles, 1), 256, SMEM_BYTES>>>(
        x, F, 0, pW1c, pY, HDIM, 0, nullptr, n, F, 1);
    fill_kernel<<<(E + 255) / 256, 256>>>(src, dst, perm, E);
    // fp16 mirror of Y (coalesced)
    {
        int n8 = n * HDIM / 8;
        cvth_kernel<<<(n8 + 255) / 256, 256>>>((const float4*)pY, (uint4*)pYh, n8);
    }
    // layer-1 aggregation (dual view, fp16 gather) + PReLU, P tf32-rounded fp32
    spmm1_kernel<<<(n + 7) / 8, 256>>>(pYh, pP, b1, a1, n);
    // layer-2 GEMMs, both views via grid.y; fp32 output, norm_out fused
    gemm_mma_kernel<<<dim3(nTiles, 2), 256, SMEM_BYTES>>>(
        pP, HDIM2, HDIM, pW2c, pHB, HDIM2, HDIM, pNormOut, n, HDIM, 0);
    // fp16 mirror of HB (coalesced)
    {
        int n8 = n * HDIM2 / 8;
        cvth_kernel<<<(n8 + 255) / 256, 256>>>((const float4*)pHB, (uint4*)pHBh, n8);
    }
    // layer-2 aggregation (fp16 gather) + PReLU + fused projection row-sum
    spmm2_kernel<<<(n + 7) / 8, 256>>>(pHBh, b2, a2, out, n);
}

// round 16
// speedup vs baseline: 1.5714x; 1.0149x over previous
#include <cuda_runtime.h>
#include <cuda_fp16.h>
#include <cstdint>

#define MAXN 50000
#define MAXE 800000
#define HDIM 96
#define HDIM2 192
#define MAXF 512

// ---------------- scratch (device globals; no allocation allowed) ----------------
__device__ int    g_cnt[3 * MAXN];              // [deg_in | deg_out | fill], one memset
__device__ int    g_rowptr[MAXN + 1];
__device__ int2   g_col2[MAXE];                 // {src, perm[src]} per edge (CSR by dst)
__device__ float  g_norm_in[MAXN];
__device__ float  g_norm_out[MAXN];
__device__ __half g_Yh[(size_t)MAXN * HDIM];    // x @ W1, fp16 (gather source)
__device__ __half g_HBh[(size_t)MAXN * HDIM2];  // layer-2 features, fp16 (gather source)
__device__ float  g_P[(size_t)MAXN * HDIM2];    // layer-1 post-PReLU, tf32-rounded
__device__ float  g_W1c[MAXF * HDIM];           // W1 pre-converted to tf32 bits
__device__ float  g_W2c[HDIM * HDIM];           // W2 pre-converted to tf32 bits
__device__ float  g_wsum[HDIM];
__device__ float  g_bmsum;

#define DEG_IN  (g_cnt)
#define DEG_OUT (g_cnt + MAXN)
#define FILLC   (g_cnt + 2 * MAXN)

// ---------------- tf32 / cp.async helpers ----------------
__device__ __forceinline__ uint32_t f2tf32(float x) {
    uint32_t u;
    asm("cvt.rna.tf32.f32 %0, %1;" : "=r"(u) : "f"(x));
    return u;
}
__device__ __forceinline__ uint32_t h2_bits(__half2 h) {
    return *reinterpret_cast<uint32_t*>(&h);
}
__device__ __forceinline__ void mma_tf32(float* c, const uint32_t* a,
                                         uint32_t b0, uint32_t b1) {
    asm volatile(
        "mma.sync.aligned.m16n8k8.row.col.f32.tf32.tf32.f32 "
        "{%0,%1,%2,%3},{%4,%5,%6,%7},{%8,%9},{%0,%1,%2,%3};"
        : "+f"(c[0]), "+f"(c[1]), "+f"(c[2]), "+f"(c[3])
        : "r"(a[0]), "r"(a[1]), "r"(a[2]), "r"(a[3]), "r"(b0), "r"(b1));
}
__device__ __forceinline__ uint32_t smem_u32(const void* p) {
    uint32_t a;
    asm("{ .reg .u64 t; cvta.to.shared.u64 t, %1; cvt.u32.u64 %0, t; }" : "=r"(a) : "l"(p));
    return a;
}
// 16B async copy; sz=0 -> zero-fill destination
__device__ __forceinline__ void cpa16(uint32_t saddr, const void* gaddr, uint32_t sz) {
    asm volatile("cp.async.cg.shared.global [%0], [%1], 16, %2;"
                 :: "r"(saddr), "l"(gaddr), "r"(sz));
}
#define CP_COMMIT() asm volatile("cp.async.commit_group;" ::: "memory")
#define CP_WAIT1()  asm volatile("cp.async.wait_group 1;" ::: "memory")

// ---------------- small setup kernels ----------------
__global__ void degree_kernel(const int* __restrict__ src, const int* __restrict__ dst, int e) {
    int i = blockIdx.x * blockDim.x + threadIdx.x;
    if (i < e) {
        atomicAdd(&DEG_OUT[src[i]], 1);
        atomicAdd(&DEG_IN[dst[i]], 1);
    }
}

// scan (rowptr + norms) + Wm row-sums + W1/W2 tf32 pre-conversion, single block
__global__ void scanw_kernel(int n, const float* __restrict__ Wm, const float* __restrict__ bm,
                             const float* __restrict__ W1, const float* __restrict__ W2,
                             int n1, int n2) {
    __shared__ int ssum[1024];
    int t = threadIdx.x;

    for (int i = t; i < n1; i += 1024) g_W1c[i] = __uint_as_float(f2tf32(W1[i]));
    for (int i = t; i < n2; i += 1024) g_W2c[i] = __uint_as_float(f2tf32(W2[i]));

    if (t < HDIM) {
        float s = 0.f;
        #pragma unroll 8
        for (int j = 0; j < HDIM; j++) s += Wm[t * HDIM + j];
        g_wsum[t] = s;
    }
    if (t == 0) {
        float s = 0.f;
        for (int j = 0; j < HDIM; j++) s += bm[j];
        g_bmsum = s;
    }

    int chunk = (n + 1023) / 1024;
    int beg = min(t * chunk, n);
    int end = min(beg + chunk, n);
    int s = 0;
    for (int i = beg; i < end; i++) s += DEG_IN[i];
    ssum[t] = s;
    __syncthreads();
    for (int off = 1; off < 1024; off <<= 1) {
        int v = (t >= off) ? ssum[t - off] : 0;
        __syncthreads();
        ssum[t] += v;
        __syncthreads();
    }
    int run = ssum[t] - s;
    for (int i = beg; i < end; i++) { g_rowptr[i] = run; run += DEG_IN[i]; }
    if (end == n) g_rowptr[n] = run;

    for (int i = beg; i < end; i++) {
        g_norm_in[i]  = rsqrtf((float)max(DEG_IN[i], 1));
        g_norm_out[i] = rsqrtf((float)max(DEG_OUT[i], 1));
    }
}

__global__ void fill_kernel(const int* __restrict__ src, const int* __restrict__ dst,
                            const int* __restrict__ perm, int e) {
    int i = blockIdx.x * blockDim.x + threadIdx.x;
    if (i < e) {
        int d = dst[i];
        int s = src[i];
        int pos = g_rowptr[d] + atomicAdd(&FILLC[d], 1);
        g_col2[pos] = make_int2(s, perm[s]);
    }
}

// ---------------- tf32 mma.sync GEMM, 2-stage cp.async, 3 CTAs/SM, fp16 output --------
// Ch[m][0..95] = half( rowscale[m]*(A[m,:K] @ B[K,96]) ); B pre-converted tf32 bits.
// CTA tile 128x96, 8 warps (4m x 2n), warp tile 32x48 (2x6 m16n8k8 atoms).
// Epilogue stages accs as half2 in smem, then writes coalesced 16B rows (avoids the
// scattered-STG.32 penalty measured in R12).
#define ASTR 36
#define BSTR 104
#define ABUF (128 * ASTR)              // 4608 floats
#define STAGEF (ABUF + 32 * BSTR)      // 7936 floats = 31744 B per stage
#define NSTAGE 2
#define HTSTR 50                        // half2 stride per row in staging tile
__global__ __launch_bounds__(256, 3) void gemm_mma_kernel(
    const float* __restrict__ A, int lda, int viewA,
    const float* __restrict__ B,
    __half* __restrict__ Ch, int ldc, int viewC,
    const float* __restrict__ rowscale,
    int M, int K, int cvtA)
{
    extern __shared__ float smf[];
    uint32_t sbase = smem_u32(smf);

    int tid = threadIdx.x;
    int wid = tid >> 5, lane = tid & 31;
    int g = lane >> 2, t = lane & 3;
    int wm = (wid & 3) * 32;
    int wn = (wid >> 2) * 48;
    int row0 = blockIdx.x * 128;
    A += (size_t)blockIdx.y * viewA;
    Ch += (size_t)blockIdx.y * viewC;

    float acc[2][6][4];
    #pragma unroll
    for (int ma = 0; ma < 2; ma++)
        #pragma unroll
        for (int na = 0; na < 6; na++)
            #pragma unroll
            for (int c = 0; c < 4; c++) acc[ma][na][c] = 0.f;

    int qa = tid & 7;
    int ra = tid >> 3;
    int nchunks = (K + 31) >> 5;

    auto load = [&](int i) {
        int k0 = i << 5;
        uint32_t st = sbase + (uint32_t)(i & 1) * (STAGEF * 4);
        #pragma unroll
        for (int j = 0; j < 4; j++) {
            int r = ra + 32 * j;
            int gr = row0 + r;
            int kc = k0 + 4 * qa;
            uint32_t ok = (gr < M && kc + 4 <= K) ? 16u : 0u;
            const float* gp = ok ? (A + (size_t)gr * lda + kc) : A;
            cpa16(st + (uint32_t)(r * ASTR + 4 * qa) * 4, gp, ok);
        }
        #pragma unroll
        for (int j = 0; j < 3; j++) {
            int idx = tid + j * 256;
            int kk = idx / 24, fc = idx - kk * 24;
            uint32_t ok = (k0 + kk < K) ? 16u : 0u;
            const float* gp = ok ? (B + (size_t)(k0 + kk) * HDIM + 4 * fc) : B;
            cpa16(st + (uint32_t)(ABUF + kk * BSTR + 4 * fc) * 4, gp, ok);
        }
    };

    load(0); CP_COMMIT();
    if (nchunks > 1) load(1);
    CP_COMMIT();

    for (int i = 0; i < nchunks; i++) {
        CP_WAIT1();
        __syncthreads();

        const float* Asm = smf + (i & 1) * STAGEF;
        const float* Bsm = Asm + ABUF;
        #pragma unroll
        for (int ks = 0; ks < 4; ks++) {
            int k = ks * 8;
            uint32_t ar[2][4];
            #pragma unroll
            for (int ma = 0; ma < 2; ma++) {
                int rb = (wm + 16 * ma + g) * ASTR + k + t;
                ar[ma][0] = __float_as_uint(Asm[rb]);
                ar[ma][1] = __float_as_uint(Asm[rb + 8 * ASTR]);
                ar[ma][2] = __float_as_uint(Asm[rb + 4]);
                ar[ma][3] = __float_as_uint(Asm[rb + 8 * ASTR + 4]);
                if (cvtA) {
                    #pragma unroll
                    for (int u = 0; u < 4; u++)
                        ar[ma][u] = f2tf32(__uint_as_float(ar[ma][u]));
                }
            }
            int kb0 = (k + t) * BSTR, kb1 = (k + t + 4) * BSTR;
            #pragma unroll
            for (int na = 0; na < 6; na++) {
                int col = wn + 8 * na + g;
                uint32_t b0 = __float_as_uint(Bsm[kb0 + col]);
                uint32_t b1 = __float_as_uint(Bsm[kb1 + col]);
                mma_tf32(acc[0][na], ar[0], b0, b1);
                mma_tf32(acc[1][na], ar[1], b0, b1);
            }
        }
        __syncthreads();
        if (i + 2 < nchunks) load(i + 2);
        CP_COMMIT();
    }

    // ---- staged fp16 epilogue: accs -> smem half2 tile -> coalesced global writes ----
    __syncthreads();                       // mainloop smem dead; reuse as staging tile
    __half2* HT = (__half2*)smf;           // [128][HTSTR]
    #pragma unroll
    for (int ma = 0; ma < 2; ma++) {
        int lr0 = wm + 16 * ma + g;
        int lr1 = lr0 + 8;
        float s0 = 1.f, s1 = 1.f;
        if (rowscale) {
            int r0g = row0 + lr0, r1g = row0 + lr1;
            if (r0g < M) s0 = rowscale[r0g];
            if (r1g < M) s1 = rowscale[r1g];
        }
        #pragma unroll
        for (int na = 0; na < 6; na++) {
            int c2 = wn / 2 + 4 * na + t;
            HT[lr0 * HTSTR + c2] = __floats2half2_rn(acc[ma][na][0] * s0, acc[ma][na][1] * s0);
            HT[lr1 * HTSTR + c2] = __floats2half2_rn(acc[ma][na][2] * s1, acc[ma][na][3] * s1);
        }
    }
    __syncthreads();
    // 128 rows x 12 uint4 (96 halves) = 1536 writes, 256 threads -> 6 each
    #pragma unroll
    for (int j = 0; j < 6; j++) {
        int idx = tid + j * 256;
        int r = idx / 12, q = idx - r * 12;
        int gr = row0 + r;
        if (gr < M) {
            __half2 a0 = HT[r * HTSTR + 4 * q + 0];
            __half2 a1 = HT[r * HTSTR + 4 * q + 1];
            __half2 a2 = HT[r * HTSTR + 4 * q + 2];
            __half2 a3 = HT[r * HTSTR + 4 * q + 3];
            uint4 o;
            o.x = h2_bits(a0); o.y = h2_bits(a1); o.z = h2_bits(a2); o.w = h2_bits(a3);
            *(uint4*)&Ch[(size_t)gr * ldc + 8 * q] = o;
        }
    }
}

// ---------------- layer-1 aggregation: gathers Yh (fp16), dual view, half-warp each ----
// Writes P pre-rounded to tf32 bits so gemm2 needs no conversion.
__global__ __launch_bounds__(256) void spmm1_kernel(
    const __half* __restrict__ Yh, float* __restrict__ Pout,
    const float* __restrict__ b, const float* __restrict__ a, int n)
{
    int gw = (blockIdx.x * blockDim.x + threadIdx.x) >> 5;
    int lane = threadIdx.x & 31;
    if (gw >= n) return;
    int hv = lane >> 4;          // 0: view1 (Y[s]), 1: view2 (Y[perm[s]])
    int l = lane & 15;

    int beg = g_rowptr[gw], end = g_rowptr[gw + 1];
    float2 acc0 = {0.f, 0.f}, acc1 = {0.f, 0.f}, acc2 = {0.f, 0.f};

    int e = beg;
    for (; e + 3 < end; e += 4) {
        int2 sp[4];
        #pragma unroll
        for (int q = 0; q < 4; q++) sp[q] = g_col2[e + q];
        float ns[4];
        #pragma unroll
        for (int q = 0; q < 4; q++) ns[q] = g_norm_out[sp[q].x];
        __half2 u[4][3];
        #pragma unroll
        for (int q = 0; q < 4; q++) {
            int s = hv ? sp[q].y : sp[q].x;
            const __half2* h = (const __half2*)(Yh + (size_t)s * HDIM);
            u[q][0] = h[l]; u[q][1] = h[l + 16]; u[q][2] = h[l + 32];
        }
        #pragma unroll
        for (int q = 0; q < 4; q++) {
            float2 f0 = __half22float2(u[q][0]);
            float2 f1 = __half22float2(u[q][1]);
            float2 f2 = __half22float2(u[q][2]);
            acc0.x += ns[q] * f0.x; acc0.y += ns[q] * f0.y;
            acc1.x += ns[q] * f1.x; acc1.y += ns[q] * f1.y;
            acc2.x += ns[q] * f2.x; acc2.y += ns[q] * f2.y;
        }
    }
    for (; e < end; e++) {
        int2 sp0 = g_col2[e];
        float ns0 = g_norm_out[sp0.x];
        int s0 = hv ? sp0.y : sp0.x;
        const __half2* h0 = (const __half2*)(Yh + (size_t)s0 * HDIM);
        float2 f0 = __half22float2(h0[l]);
        float2 f1 = __half22float2(h0[l + 16]);
        float2 f2 = __half22float2(h0[l + 32]);
        acc0.x += ns0 * f0.x; acc0.y += ns0 * f0.y;
        acc1.x += ns0 * f1.x; acc1.y += ns0 * f1.y;
        acc2.x += ns0 * f2.x; acc2.y += ns0 * f2.y;
    }

    float ni = g_norm_in[gw];
    float2* po = (float2*)(Pout + (size_t)gw * HDIM2);

    #pragma unroll
    for (int j = 0; j < 3; j++) {
        int idx = l + 16 * j;
        int c0 = 2 * idx;
        float2 acc = (j == 0) ? acc0 : (j == 1) ? acc1 : acc2;
        float h0 = acc.x * ni + b[c0];
        float h1 = acc.y * ni + b[c0 + 1];
        float z0 = (h0 >= 0.f) ? h0 : a[c0] * h0;
        float z1 = (h1 >= 0.f) ? h1 : a[c0 + 1] * h1;
        z0 = __uint_as_float(f2tf32(z0));
        z1 = __uint_as_float(f2tf32(z1));
        po[hv * 48 + idx] = make_float2(z0, z1);
    }
}

// ---------------- layer-2 aggregation (fp16 gather) + PReLU + fused projection sum -----
__global__ __launch_bounds__(256) void spmm2_kernel(
    const __half* __restrict__ Hh,
    const float* __restrict__ b, const float* __restrict__ a,
    float* __restrict__ out, int n)
{
    int gw = (blockIdx.x * blockDim.x + threadIdx.x) >> 5;
    int lane = threadIdx.x & 31;
    if (gw >= n) return;

    int beg = g_rowptr[gw], end = g_rowptr[gw + 1];
    float2 acc0 = {0.f, 0.f}, acc1 = {0.f, 0.f}, acc2 = {0.f, 0.f};

    int e = beg;
    for (; e + 3 < end; e += 4) {
        __half2 u[4][3];
        #pragma unroll
        for (int q = 0; q < 4; q++) {
            const __half2* h = (const __half2*)(Hh + (size_t)g_col2[e + q].x * HDIM2);
            u[q][0] = h[lane]; u[q][1] = h[lane + 32]; u[q][2] = h[lane + 64];
        }
        #pragma unroll
        for (int q = 0; q < 4; q++) {
            float2 f0 = __half22float2(u[q][0]);
            float2 f1 = __half22float2(u[q][1]);
            float2 f2 = __half22float2(u[q][2]);
            acc0.x += f0.x; acc0.y += f0.y;
            acc1.x += f1.x; acc1.y += f1.y;
            acc2.x += f2.x; acc2.y += f2.y;
        }
    }
    for (; e < end; e++) {
        const __half2* h0 = (const __half2*)(Hh + (size_t)g_col2[e].x * HDIM2);
        float2 f0 = __half22float2(h0[lane]);
        float2 f1 = __half22float2(h0[lane + 32]);
        float2 f2 = __half22float2(h0[lane + 64]);
        acc0.x += f0.x; acc0.y += f0.y;
        acc1.x += f1.x; acc1.y += f1.y;
        acc2.x += f2.x; acc2.y += f2.y;
    }

    float ni = g_norm_in[gw];
    float s1 = 0.f, s2 = 0.f;

    #pragma unroll
    for (int j = 0; j < 3; j++) {
        int idx = lane + 32 * j;
        float2 acc = (j == 0) ? acc0 : (j == 1) ? acc1 : acc2;
        int v = idx >= 48;
        int c0 = 2 * idx - 96 * v;
        float h0 = acc.x * ni + b[c0];
        float h1 = acc.y * ni + b[c0 + 1];
        float z0 = (h0 >= 0.f) ? h0 : a[c0] * h0;
        float z1 = (h1 >= 0.f) ? h1 : a[c0 + 1] * h1;
        float contrib = z0 * g_wsum[c0] + z1 * g_wsum[c0 + 1];
        if (v) s2 += contrib; else s1 += contrib;
    }

    #pragma unroll
    for (int off = 16; off > 0; off >>= 1) {
        s1 += __shfl_xor_sync(0xffffffff, s1, off);
        s2 += __shfl_xor_sync(0xffffffff, s2, off);
    }
    if (lane == 0) {
        out[gw]     = s1 + g_bmsum;
        out[n + gw] = s2 + g_bmsum;
    }
}

// ---------------- launch ----------------
extern "C" void kernel_launch(void* const* d_in, const int* in_sizes, int n_in,
                              void* d_out, int out_size) {
    const float* x   = (const float*)d_in[0];
    const int*   src = (const int*)  d_in[1];
    const int*   dst = (const int*)  d_in[2];
    const int*   perm= (const int*)  d_in[3];
    const float* W1  = (const float*)d_in[4];
    const float* b1  = (const float*)d_in[5];
    const float* a1  = (const float*)d_in[6];
    const float* W2  = (const float*)d_in[7];
    const float* b2  = (const float*)d_in[8];
    const float* a2  = (const float*)d_in[9];
    const float* Wm  = (const float*)d_in[10];
    const float* bm  = (const float*)d_in[11];
    float* out = (float*)d_out;

    int E = in_sizes[1];
    int n = in_sizes[3];
    int F = in_sizes[0] / n;

    float *pP, *pNormOut, *pW1c, *pW2c;
    __half *pYh, *pHBh;
    int *pCnt;
    cudaGetSymbolAddress((void**)&pYh, g_Yh);
    cudaGetSymbolAddress((void**)&pHBh, g_HBh);
    cudaGetSymbolAddress((void**)&pP, g_P);
    cudaGetSymbolAddress((void**)&pNormOut, g_norm_out);
    cudaGetSymbolAddress((void**)&pCnt, g_cnt);
    cudaGetSymbolAddress((void**)&pW1c, g_W1c);
    cudaGetSymbolAddress((void**)&pW2c, g_W2c);

    const int SMEM_BYTES = NSTAGE * STAGEF * 4;   // 63488 (>= 128*HTSTR*4 staging)
    static int inited = 0;
    if (!inited) {
        cudaFuncSetAttribute(gemm_mma_kernel,
                             cudaFuncAttributeMaxDynamicSharedMemorySize, SMEM_BYTES);
        inited = 1;
    }

    int nTiles = (n + 127) / 128;

    cudaMemsetAsync(pCnt, 0, 3 * MAXN * sizeof(int));

    degree_kernel<<<(E + 255) / 256, 256>>>(src, dst, E);
    // scan + norms + Wm rowsum + W1/W2 tf32 pre-conversion (merged)
    scanw_kernel<<<1, 1024>>>(n, Wm, bm, W1, W2, F * HDIM, HDIM * HDIM);
    // Yh = half( X @ W1c )  (tf32 mma.sync, staged fp16 epilogue)
    gemm_mma_kernel<<<dim3(nTiles, 1), 256, SMEM_BYTES>>>(
        x, F, 0, pW1c, pYh, HDIM, 0, nullptr, n, F, 1);
    fill_kernel<<<(E + 255) / 256, 256>>>(src, dst, perm, E);
    // layer-1 aggregation (dual view, fp16 gather) + PReLU, P tf32-rounded fp32
    spmm1_kernel<<<(n + 7) / 8, 256>>>(pYh, pP, b1, a1, n);
    // layer-2 GEMMs, both views via grid.y; fp16 output, norm_out fused in epilogue
    gemm_mma_kernel<<<dim3(nTiles, 2), 256, SMEM_BYTES>>>(
        pP, HDIM2, HDIM, pW2c, pHBh, HDIM2, HDIM, pNormOut, n, HDIM, 0);
    // layer-2 aggregation (fp16 gather) + PReLU + fused projection row-sum
    spmm2_kernel<<<(n + 7) / 8, 256>>>(pHBh, b2, a2, out, n);
}